// round 17
// baseline (speedup 1.0000x reference)
#include <cuda_runtime.h>
#include <math.h>

#define N_NODES 4096
#define NFEAT   128
#define NHID    128
#define NHEADS  4
#define NCLASS  32
#define KEDGE   32
#define ALPHA_LRELU 0.2f

// ---------------- scratch (no allocations allowed) ----------------
__device__ float g_h  [N_NODES * NHEADS * NHID];   // [n][head*128+d]
__device__ float g_xc [N_NODES * NHEADS * NHID];   // [n][head*128+d]
__device__ float g_f1p[2 * NHEADS * N_NODES];      // partial dots, slot = column-half
__device__ float g_f2p[2 * NHEADS * N_NODES];
__device__ float g_h2 [N_NODES * NCLASS];
__device__ float g_f1o[N_NODES];
__device__ float g_f2o[N_NODES];

// ---------------- K1: h = x @ concat(Ws), fused partial f1/f2 (R13-proven) -----
__global__ void k_gemm1(const float* __restrict__ X, const float* __restrict__ Ws,
                        const float* __restrict__ a) {
    __shared__ __align__(16) float As[64][68];  // [k][m]
    __shared__ __align__(16) float Bs[64][68];  // [k][n]
    int bx = blockIdx.x;
    int by = blockIdx.y;
    int n0 = bx * 64;
    int head = n0 >> 7;
    int nloc = n0 & 127;
    int slot = bx & 1;
    const float* B = Ws + head * NFEAT * NHID;
    int m0 = by * 64;
    int tid = threadIdx.x;
    int tx = tid & 15, ty = tid >> 4;

    float acc[4][4] = {};
    for (int kc = 0; kc < NFEAT; kc += 64) {
        #pragma unroll
        for (int t = 0; t < 16; t++) {
            int e = t * 256 + tid;
            { int k = e & 63, m = e >> 6;
              As[k][m] = X[(m0 + m) * NFEAT + kc + k]; }
            { int n = e & 63, k = e >> 6;
              Bs[k][n] = B[(kc + k) * NHID + nloc + n]; }
        }
        __syncthreads();
        #pragma unroll 16
        for (int kk = 0; kk < 64; kk++) {
            float4 av4 = *(const float4*)&As[kk][ty * 4];
            float4 bv4 = *(const float4*)&Bs[kk][tx * 4];
            float av[4] = {av4.x, av4.y, av4.z, av4.w};
            float bv[4] = {bv4.x, bv4.y, bv4.z, bv4.w};
            #pragma unroll
            for (int i = 0; i < 4; i++)
                #pragma unroll
                for (int j = 0; j < 4; j++)
                    acc[i][j] += av[i] * bv[j];
        }
        __syncthreads();
    }
    float a1j[4], a2j[4];
    #pragma unroll
    for (int j = 0; j < 4; j++) {
        int col = nloc + tx * 4 + j;
        a1j[j] = a[head * 256 + col];
        a2j[j] = a[head * 256 + 128 + col];
    }
    #pragma unroll
    for (int i = 0; i < 4; i++) {
        int row = m0 + ty * 4 + i;
        float4 v = make_float4(acc[i][0], acc[i][1], acc[i][2], acc[i][3]);
        *(float4*)&g_h[(size_t)row * 512 + n0 + tx * 4] = v;
        float s1 = 0.f, s2 = 0.f;
        #pragma unroll
        for (int j = 0; j < 4; j++) { s1 += acc[i][j] * a1j[j]; s2 += acc[i][j] * a2j[j]; }
        #pragma unroll
        for (int o = 8; o; o >>= 1) {
            s1 += __shfl_xor_sync(0xffffffffu, s1, o);
            s2 += __shfl_xor_sync(0xffffffffu, s2, o);
        }
        if (tx == 0) {
            g_f1p[slot * 16384 + head * N_NODES + row] = s1;
            g_f2p[slot * 16384 + head * N_NODES + row] = s2;
        }
    }
}

// ---------------- K2: layer-1 attention, inline dedup + fixed-32 2-chain gather --
// grid 4096, block 128: warp = head, lane participates in dedup + d-chunk gather
__global__ void k_attn1(const int* __restrict__ edge) {
    int row  = blockIdx.x;
    int head = threadIdx.x >> 5;
    int lane = threadIdx.x & 31;
    int base = row & ~1023;

    // inline dedup (R8/R12-proven): weight 0 on dup/invalid lanes
    int e = edge[row * KEDGE + lane];           // 128B, L1-broadcast across 4 warps
    bool valid = (e >= 0);
    unsigned key = valid ? (unsigned)e : (0x40000000u + (unsigned)lane);
    unsigned grp = __match_any_sync(0xffffffffu, key);
    bool uniq = valid && ((__ffs(grp) - 1) == lane);
    int j = valid ? e : 0;

    float p = 0.f;
    if (uniq) {
        float f1 = g_f1p[head * N_NODES + row] + g_f1p[16384 + head * N_NODES + row];
        float f2 = g_f2p[head * N_NODES + base + e] +
                   g_f2p[16384 + head * N_NODES + base + e];
        float t = f1 + f2;
        float la = (t > 0.f) ? t : ALPHA_LRELU * t;   // bounded: exp safe w/o max-sub
        p = __expf(la);
    }
    float s = p;
    #pragma unroll
    for (int o = 16; o; o >>= 1) s += __shfl_xor_sync(0xffffffffu, s, o);
    float wgt = p / s;                                 // 0 for dup/invalid lanes

    const float* tl = g_h + (size_t)base * 512 + head * 128 + lane * 4;
    float4 acc0 = make_float4(0.f, 0.f, 0.f, 0.f);
    float4 acc1 = make_float4(0.f, 0.f, 0.f, 0.f);
    // fixed trip count + two independent accumulate chains (2x ILP)
    #pragma unroll
    for (int k = 0; k < KEDGE; k += 2) {
        float w0 = __shfl_sync(0xffffffffu, wgt, k);
        int   j0 = __shfl_sync(0xffffffffu, j, k);
        float w1 = __shfl_sync(0xffffffffu, wgt, k + 1);
        int   j1 = __shfl_sync(0xffffffffu, j, k + 1);
        float4 h0 = *(const float4*)&tl[j0 * 512];
        float4 h1 = *(const float4*)&tl[j1 * 512];
        acc0.x += w0 * h0.x; acc0.y += w0 * h0.y;
        acc0.z += w0 * h0.z; acc0.w += w0 * h0.w;
        acc1.x += w1 * h1.x; acc1.y += w1 * h1.y;
        acc1.z += w1 * h1.z; acc1.w += w1 * h1.w;
    }
    float4 acc = make_float4(acc0.x + acc1.x, acc0.y + acc1.y,
                             acc0.z + acc1.z, acc0.w + acc1.w);
    float4 o4;
    o4.x = acc.x > 0.f ? acc.x : expm1f(acc.x);
    o4.y = acc.y > 0.f ? acc.y : expm1f(acc.y);
    o4.z = acc.z > 0.f ? acc.z : expm1f(acc.z);
    o4.w = acc.w > 0.f ? acc.w : expm1f(acc.w);
    *(float4*)&g_xc[(size_t)row * 512 + head * 128 + lane * 4] = o4;
}

// ---------------- K3: h2 = xc @ W_out, 0.5 LDS/FMA (R13-proven) -----------------
__global__ void k_gemm2(const float* __restrict__ W, const float* __restrict__ a_out) {
    __shared__ __align__(16) float  Xs[32][132];
    __shared__ __align__(16) float4 Wsm4[128][8];
    int r0   = blockIdx.x * 32;
    int tid  = threadIdx.x;
    int lane = tid & 31, warp = tid >> 5;
    int r    = lane >> 3;
    int c8   = lane & 7;
    int lrow = warp * 4 + r;

    float4 acc = make_float4(0.f, 0.f, 0.f, 0.f);
    for (int kc = 0; kc < 512; kc += 128) {
        #pragma unroll
        for (int t = 0; t < 4; t++) {
            int idx = tid + t * 256;
            { int rr = idx >> 5, cc = idx & 31;
              *(float4*)&Xs[rr][cc * 4] =
                  *(const float4*)&g_xc[(size_t)(r0 + rr) * 512 + kc + cc * 4]; }
            { int kk = idx >> 3, c = idx & 7;
              Wsm4[kk][c] = ((const float4*)W)[(kc + kk) * 8 + c]; }
        }
        __syncthreads();
        #pragma unroll 8
        for (int kk = 0; kk < 128; kk++) {
            float  xv = Xs[lrow][kk];
            float4 wv = Wsm4[kk][c8];
            acc.x += xv * wv.x; acc.y += xv * wv.y;
            acc.z += xv * wv.z; acc.w += xv * wv.w;
        }
        __syncthreads();
    }
    int row = r0 + lrow;
    *(float4*)&g_h2[row * 32 + c8 * 4] = acc;

    float4 a1 = *(const float4*)&a_out[c8 * 4];
    float4 a2 = *(const float4*)&a_out[32 + c8 * 4];
    float s1 = acc.x * a1.x + acc.y * a1.y + acc.z * a1.z + acc.w * a1.w;
    float s2 = acc.x * a2.x + acc.y * a2.y + acc.z * a2.z + acc.w * a2.w;
    #pragma unroll
    for (int o = 4; o; o >>= 1) {
        s1 += __shfl_xor_sync(0xffffffffu, s1, o);
        s2 += __shfl_xor_sync(0xffffffffu, s2, o);
    }
    if (c8 == 0) { g_f1o[row] = s1; g_f2o[row] = s2; }
}

// ---------------- K4: layer-2 attention + elu + log_softmax (inline dedup) ------
__global__ void k_attn2(const int* __restrict__ edge, float* __restrict__ out) {
    int row  = blockIdx.x * 4 + (threadIdx.x >> 5);
    int lane = threadIdx.x & 31;
    int base = row & ~1023;

    int e = edge[row * KEDGE + lane];
    bool valid = (e >= 0);
    unsigned key = valid ? (unsigned)e : (0x40000000u + (unsigned)lane);
    unsigned grp = __match_any_sync(0xffffffffu, key);
    bool uniq = valid && ((__ffs(grp) - 1) == lane);
    int j = valid ? e : 0;

    float p = 0.f;
    if (uniq) {
        float t = g_f1o[row] + g_f2o[base + e];
        float la = (t > 0.f) ? t : ALPHA_LRELU * t;
        p = __expf(la);
    }
    float s = p;
    #pragma unroll
    for (int o = 16; o; o >>= 1) s += __shfl_xor_sync(0xffffffffu, s, o);
    float wgt = p / s;

    const float* hb = g_h2 + (size_t)base * 32 + lane;
    float acc0 = 0.f, acc1 = 0.f;
    #pragma unroll
    for (int k = 0; k < KEDGE; k += 2) {
        float w0 = __shfl_sync(0xffffffffu, wgt, k);
        int   j0 = __shfl_sync(0xffffffffu, j, k);
        float w1 = __shfl_sync(0xffffffffu, wgt, k + 1);
        int   j1 = __shfl_sync(0xffffffffu, j, k + 1);
        acc0 += w0 * hb[j0 * 32];
        acc1 += w1 * hb[j1 * 32];
    }
    float acc = acc0 + acc1;
    float v = acc > 0.f ? acc : expm1f(acc);
    float m2 = v;
    #pragma unroll
    for (int o = 16; o; o >>= 1) m2 = fmaxf(m2, __shfl_xor_sync(0xffffffffu, m2, o));
    float se = __expf(v - m2);
    #pragma unroll
    for (int o = 16; o; o >>= 1) se += __shfl_xor_sync(0xffffffffu, se, o);
    out[row * 32 + lane] = v - m2 - logf(se);
}

// ---------------- launch ----------------
extern "C" void kernel_launch(void* const* d_in, const int* in_sizes, int n_in,
                              void* d_out, int out_size) {
    const float* x     = (const float*)d_in[0];
    const int*   edge  = (const int*)d_in[1];
    const float* Ws    = (const float*)d_in[3];
    const float* a     = (const float*)d_in[4];
    const float* W_out = (const float*)d_in[5];
    const float* a_out = (const float*)d_in[6];
    float* out = (float*)d_out;

    dim3 g1(8, 64);
    k_gemm1<<<g1, 256>>>(x, Ws, a);
    k_attn1<<<N_NODES, 128>>>(edge);
    k_gemm2<<<128, 256>>>(W_out, a_out);
    k_attn2<<<N_NODES / 4, 128>>>(edge, out);
}